// round 14
// baseline (speedup 1.0000x reference)
#include <cuda_runtime.h>
#include <cuda_bf16.h>
#include <cstdint>

#define NP    64
#define NANG  2016     // 64*63/2
#define SEG   504      // NANG / 4
#define PITCH 36       // u32 per staged 64-bf16 column: conflict-free + 16B-aligned
#define CPB   256      // columns per CTA

// Pre-packed m16n8k16 A-fragments of (mus-scaled) R, hi/lo bf16 split.
// Slot = (i_tile*4 + s_ktile)*32 + lane ; .x=a0 .y=a1 .z=a2 .w=a3
__device__ uint4 g_fragH[512];
__device__ uint4 g_fragL[512];

// ---------------------------------------------------------------------------
// helpers
// ---------------------------------------------------------------------------
__device__ __forceinline__ uint32_t pack_bf16x2(float lo, float hi) {
    uint32_t r;
    asm("cvt.rn.bf16x2.f32 %0, %1, %2;" : "=r"(r) : "f"(hi), "f"(lo));
    return r;
}
__device__ __forceinline__ float bf16_hi_val(float v) {
    return __bfloat162float(__float2bfloat16(v));
}
__device__ __forceinline__ void mma_bf16(float& d0, float& d1, float& d2, float& d3,
                                         uint32_t a0, uint32_t a1, uint32_t a2, uint32_t a3,
                                         uint32_t b0, uint32_t b1) {
    asm("mma.sync.aligned.m16n8k16.row.col.f32.bf16.bf16.f32 "
        "{%0,%1,%2,%3}, {%4,%5,%6,%7}, {%8,%9}, {%0,%1,%2,%3};"
        : "+f"(d0), "+f"(d1), "+f"(d2), "+f"(d3)
        : "r"(a0), "r"(a1), "r"(a2), "r"(a3), "r"(b0), "r"(b1));
}

// ---------------------------------------------------------------------------
// Kernel 1: build R = P3*P2*P1*P0 (4 parallel 504-rotation segments, 3 fp32
// matmuls to combine), then emit mus-scaled hi/lo bf16 A-fragments.
// (unchanged from R11 — verified rel_err 4.4e-6)
// ---------------------------------------------------------------------------
#define BR_SMEM (16384 * 5)

__global__ void build_R_kernel(const float* __restrict__ angles,
                               const float* __restrict__ mus) {
    extern __shared__ __align__(16) char smem[];
    float2* cs = reinterpret_cast<float2*>(smem);
    float*  Pm[4];
#pragma unroll
    for (int s = 0; s < 4; ++s) Pm[s] = reinterpret_cast<float*>(smem + 16384 + s * 16384);

    const int tid  = threadIdx.x;
    const int g4   = tid >> 6;
    const int lane = tid & 63;

    for (int a = tid; a < NANG; a += 256) {
        float s, c;
        sincosf(angles[a], &s, &c);
        cs[a] = make_float2(c, s);
    }
    {
        float* Y = Pm[g4];
#pragma unroll
        for (int i = 0; i < NP; ++i) Y[i * NP + lane] = (i == lane) ? 1.0f : 0.0f;
    }
    __syncthreads();

    {
        float* Y = Pm[g4];
        const int segStart = g4 * SEG, segEnd = segStart + SEG;
        int F = 0;
        for (int t = 0; t < NP - 1; ++t) {
            const int fanLen = NP - 1 - t;
            int lo = F > segStart ? F : segStart;
            int hi = (F + fanLen) < segEnd ? (F + fanLen) : segEnd;
            if (lo < hi) {
                float vt = Y[t * NP + lane];
                int idx = lo;
                int ib = t + 1 + (lo - F);
                int cnt = hi - lo;
                const int rem = cnt & 7;
                for (int u = 0; u < rem; ++u) {
                    float2 a = cs[idx + u];
                    float vb = Y[(ib + u) * NP + lane];
                    float nb = fmaf(a.y, vt, a.x * vb);
                    vt = fmaf(a.x, vt, -a.y * vb);
                    Y[(ib + u) * NP + lane] = nb;
                }
                idx += rem; ib += rem;
                for (; idx < hi; ib += 8, idx += 8) {
                    float2 a0 = cs[idx+0], a1 = cs[idx+1], a2 = cs[idx+2], a3 = cs[idx+3];
                    float2 a4 = cs[idx+4], a5 = cs[idx+5], a6 = cs[idx+6], a7 = cs[idx+7];
                    float vb0 = Y[(ib+0)*NP+lane], vb1 = Y[(ib+1)*NP+lane];
                    float vb2 = Y[(ib+2)*NP+lane], vb3 = Y[(ib+3)*NP+lane];
                    float vb4 = Y[(ib+4)*NP+lane], vb5 = Y[(ib+5)*NP+lane];
                    float vb6 = Y[(ib+6)*NP+lane], vb7 = Y[(ib+7)*NP+lane];
                    float nb0 = fmaf(a0.y, vt, a0.x*vb0); vt = fmaf(a0.x, vt, -a0.y*vb0);
                    float nb1 = fmaf(a1.y, vt, a1.x*vb1); vt = fmaf(a1.x, vt, -a1.y*vb1);
                    float nb2 = fmaf(a2.y, vt, a2.x*vb2); vt = fmaf(a2.x, vt, -a2.y*vb2);
                    float nb3 = fmaf(a3.y, vt, a3.x*vb3); vt = fmaf(a3.x, vt, -a3.y*vb3);
                    float nb4 = fmaf(a4.y, vt, a4.x*vb4); vt = fmaf(a4.x, vt, -a4.y*vb4);
                    float nb5 = fmaf(a5.y, vt, a5.x*vb5); vt = fmaf(a5.x, vt, -a5.y*vb5);
                    float nb6 = fmaf(a6.y, vt, a6.x*vb6); vt = fmaf(a6.x, vt, -a6.y*vb6);
                    float nb7 = fmaf(a7.y, vt, a7.x*vb7); vt = fmaf(a7.x, vt, -a7.y*vb7);
                    Y[(ib+0)*NP+lane] = nb0; Y[(ib+1)*NP+lane] = nb1;
                    Y[(ib+2)*NP+lane] = nb2; Y[(ib+3)*NP+lane] = nb3;
                    Y[(ib+4)*NP+lane] = nb4; Y[(ib+5)*NP+lane] = nb5;
                    Y[(ib+6)*NP+lane] = nb6; Y[(ib+7)*NP+lane] = nb7;
                }
                Y[t * NP + lane] = vt;
            }
            F += fanLen;
            if (F >= segEnd) break;
        }
    }
    __syncthreads();

    float* T0   = reinterpret_cast<float*>(smem);
    float* T1   = Pm[0];
    float* Rfin = T0;
    const int mi = tid >> 2;
    const int jq = (tid & 3) * 16;

#define MATMUL(Cm, Am, Bm)                                                       \
    {                                                                            \
        float accm[16];                                                          \
        _Pragma("unroll")                                                        \
        for (int u = 0; u < 16; ++u) accm[u] = 0.0f;                             \
        for (int k = 0; k < NP; ++k) {                                           \
            float av = (Am)[mi * NP + k];                                        \
            const float4* br = reinterpret_cast<const float4*>(&(Bm)[k * NP + jq]); \
            float4 b0 = br[0], b1 = br[1], b2 = br[2], b3 = br[3];               \
            accm[0]  = fmaf(av, b0.x, accm[0]);  accm[1]  = fmaf(av, b0.y, accm[1]);  \
            accm[2]  = fmaf(av, b0.z, accm[2]);  accm[3]  = fmaf(av, b0.w, accm[3]);  \
            accm[4]  = fmaf(av, b1.x, accm[4]);  accm[5]  = fmaf(av, b1.y, accm[5]);  \
            accm[6]  = fmaf(av, b1.z, accm[6]);  accm[7]  = fmaf(av, b1.w, accm[7]);  \
            accm[8]  = fmaf(av, b2.x, accm[8]);  accm[9]  = fmaf(av, b2.y, accm[9]);  \
            accm[10] = fmaf(av, b2.z, accm[10]); accm[11] = fmaf(av, b2.w, accm[11]); \
            accm[12] = fmaf(av, b3.x, accm[12]); accm[13] = fmaf(av, b3.y, accm[13]); \
            accm[14] = fmaf(av, b3.z, accm[14]); accm[15] = fmaf(av, b3.w, accm[15]); \
        }                                                                        \
        __syncthreads();                                                         \
        _Pragma("unroll")                                                        \
        for (int u = 0; u < 16; ++u) (Cm)[mi * NP + jq + u] = accm[u];           \
        __syncthreads();                                                         \
    }

    MATMUL(T0, Pm[1], Pm[0]);
    MATMUL(T1, Pm[2], T0);
    MATMUL(Rfin, Pm[3], T1);
#undef MATMUL

#pragma unroll
    for (int pass = 0; pass < 2; ++pass) {
        const int slot = tid + pass * 256;
        const int is = slot >> 5, ln = slot & 31;
        const int it = is >> 2, s = is & 3;
        const int g = ln >> 2, t = ln & 3;
        const int r0 = 16 * it + g, r1 = r0 + 8;
        const int c0 = 16 * s + 2 * t, c1 = c0 + 8;
        const float m0 = mus[r0], m1 = mus[r1];
        float v00 = Rfin[r0 * NP + c0] * m0,     v01 = Rfin[r0 * NP + c0 + 1] * m0;
        float v10 = Rfin[r1 * NP + c0] * m1,     v11 = Rfin[r1 * NP + c0 + 1] * m1;
        float v02 = Rfin[r0 * NP + c1] * m0,     v03 = Rfin[r0 * NP + c1 + 1] * m0;
        float v12 = Rfin[r1 * NP + c1] * m1,     v13 = Rfin[r1 * NP + c1 + 1] * m1;
        uint4 hi, lo;
        hi.x = pack_bf16x2(v00, v01); hi.y = pack_bf16x2(v10, v11);
        hi.z = pack_bf16x2(v02, v03); hi.w = pack_bf16x2(v12, v13);
        lo.x = pack_bf16x2(v00 - bf16_hi_val(v00), v01 - bf16_hi_val(v01));
        lo.y = pack_bf16x2(v10 - bf16_hi_val(v10), v11 - bf16_hi_val(v11));
        lo.z = pack_bf16x2(v02 - bf16_hi_val(v02), v03 - bf16_hi_val(v03));
        lo.w = pack_bf16x2(v12 - bf16_hi_val(v12), v13 - bf16_hi_val(v13));
        g_fragH[slot] = hi;
        g_fragL[slot] = lo;
    }
}

// ---------------------------------------------------------------------------
// Kernel 2: out[64, N] = R @ X, warp HMMA, hi/lo split, fused 3 passes.
// v4 tiling for minimum L1 operand traffic: CTA = 64 x 256 columns, 8 warps,
// warp tile = 32 rows (2 i-tiles) x 64 cols (8 n-tiles)  ->  operand LDS
// per output drops 40% vs 64x16 warps, frag staging amortized over 2x cols.
// Staging: coalesced LDG -> convert once -> STS.128 at pitch 36 (bank-free).
// smem (u32): FRAGH 0, FRAGL 2048, XHI 4096, XLO 13312, total 22528 (90112B).
// ---------------------------------------------------------------------------
#define SM_FRAGH 0
#define SM_FRAGL 2048
#define SM_XHI   4096
#define SM_XLO   13312
#define APPLY_SMEM (22528 * 4)

__global__ __launch_bounds__(256, 2)
void apply_mma_kernel(const float* __restrict__ X,
                      float* __restrict__ out,
                      int N) {
    extern __shared__ __align__(16) uint32_t sm[];
    uint4*    fragH = reinterpret_cast<uint4*>(sm + SM_FRAGH);
    uint4*    fragL = reinterpret_cast<uint4*>(sm + SM_FRAGL);
    uint32_t* Xhi   = sm + SM_XHI;
    uint32_t* Xlo   = sm + SM_XLO;

    const int tid  = threadIdx.x;
    const int wid  = tid >> 5;
    const int lane = tid & 31;
    const int g    = lane >> 2;
    const int t    = lane & 3;
    const int mg   = wid >> 2;    // row group: i-tiles {2mg, 2mg+1}
    const int cg   = wid & 3;     // col group: columns cg*64 .. cg*64+63
    const int col0 = blockIdx.x * CPB;

    // --- Stage pre-packed R fragments (4x LDG.128 + STS.128 per thread) ---
    fragH[tid]       = g_fragH[tid];
    fragH[tid + 256] = g_fragH[tid + 256];
    fragL[tid]       = g_fragL[tid];
    fragL[tid + 256] = g_fragL[tid + 256];

    // --- Stage X tile: 256 columns x 64 k, hi/lo bf16, chunked 4x16 ---
    {
        const int c  = tid;                       // one column per thread
        const int cgl = (col0 + c < N) ? (col0 + c) : (N - 1);
        const float* xp = X + cgl;
#pragma unroll
        for (int h = 0; h < 4; ++h) {
            const int kb = h * 16;
            float v[16];
#pragma unroll
            for (int j = 0; j < 16; ++j) v[j] = xp[(size_t)(kb + j) * N];
            uint32_t hb[8], lb[8];
#pragma unroll
            for (int j = 0; j < 8; ++j) {
                float v0 = v[2 * j], v1 = v[2 * j + 1];
                hb[j] = pack_bf16x2(v0, v1);
                lb[j] = pack_bf16x2(v0 - bf16_hi_val(v0), v1 - bf16_hi_val(v1));
            }
            const int base = c * PITCH + (kb >> 1);   // 16B-aligned
            reinterpret_cast<uint4*>(&Xhi[base])[0]     = make_uint4(hb[0], hb[1], hb[2], hb[3]);
            reinterpret_cast<uint4*>(&Xhi[base + 4])[0] = make_uint4(hb[4], hb[5], hb[6], hb[7]);
            reinterpret_cast<uint4*>(&Xlo[base])[0]     = make_uint4(lb[0], lb[1], lb[2], lb[3]);
            reinterpret_cast<uint4*>(&Xlo[base + 4])[0] = make_uint4(lb[4], lb[5], lb[6], lb[7]);
        }
    }
    __syncthreads();

    // --- Accumulators: [i2][ntile][4], 64 f32 regs ---
    float acc[2][8][4];
#pragma unroll
    for (int i = 0; i < 2; ++i)
#pragma unroll
        for (int n = 0; n < 8; ++n)
#pragma unroll
            for (int r = 0; r < 4; ++r) acc[i][n][r] = 0.0f;

    // --- Fused 3-pass main loop ---
#pragma unroll
    for (int s = 0; s < 4; ++s) {
        // A-fragments for this warp's two i-tiles (loaded once per s)
        uint4 fH0 = fragH[((2 * mg + 0) * 4 + s) * 32 + lane];
        uint4 fL0 = fragL[((2 * mg + 0) * 4 + s) * 32 + lane];
        uint4 fH1 = fragH[((2 * mg + 1) * 4 + s) * 32 + lane];
        uint4 fL1 = fragL[((2 * mg + 1) * 4 + s) * 32 + lane];

#pragma unroll
        for (int nt = 0; nt < 8; ++nt) {
            const int crow = cg * 64 + nt * 8 + g;           // staged column index
            const int bi = crow * PITCH + s * 8 + t;
            uint32_t bh0 = Xhi[bi];
            uint32_t bh1 = Xhi[bi + 4];
            uint32_t bl0 = Xlo[bi];
            uint32_t bl1 = Xlo[bi + 4];

            mma_bf16(acc[0][nt][0], acc[0][nt][1], acc[0][nt][2], acc[0][nt][3],
                     fH0.x, fH0.y, fH0.z, fH0.w, bh0, bh1);
            mma_bf16(acc[0][nt][0], acc[0][nt][1], acc[0][nt][2], acc[0][nt][3],
                     fH0.x, fH0.y, fH0.z, fH0.w, bl0, bl1);
            mma_bf16(acc[0][nt][0], acc[0][nt][1], acc[0][nt][2], acc[0][nt][3],
                     fL0.x, fL0.y, fL0.z, fL0.w, bh0, bh1);
            mma_bf16(acc[1][nt][0], acc[1][nt][1], acc[1][nt][2], acc[1][nt][3],
                     fH1.x, fH1.y, fH1.z, fH1.w, bh0, bh1);
            mma_bf16(acc[1][nt][0], acc[1][nt][1], acc[1][nt][2], acc[1][nt][3],
                     fH1.x, fH1.y, fH1.z, fH1.w, bl0, bl1);
            mma_bf16(acc[1][nt][0], acc[1][nt][1], acc[1][nt][2], acc[1][nt][3],
                     fL1.x, fL1.y, fL1.z, fL1.w, bh0, bh1);
        }
    }

    // --- Epilogue: adjacent-column float2 stores ---
#pragma unroll
    for (int i = 0; i < 2; ++i) {
        const int row = (2 * mg + i) * 16 + g;
#pragma unroll
        for (int nt = 0; nt < 8; ++nt) {
            const int colb = col0 + cg * 64 + nt * 8 + 2 * t;
            if (colb < N) {
                *reinterpret_cast<float2*>(out + (size_t)row * N + colb) =
                    make_float2(acc[i][nt][0], acc[i][nt][1]);
                *reinterpret_cast<float2*>(out + (size_t)(row + 8) * N + colb) =
                    make_float2(acc[i][nt][2], acc[i][nt][3]);
            }
        }
    }
}

// ---------------------------------------------------------------------------
// Inputs (metadata order): X [64*500000] f32, angles [2016] f32, mus [64] f32.
// Output: [64*500000] f32.
// ---------------------------------------------------------------------------
extern "C" void kernel_launch(void* const* d_in, const int* in_sizes, int n_in,
                              void* d_out, int out_size) {
    const float* X      = (const float*)d_in[0];
    const float* angles = (const float*)d_in[1];
    const float* mus    = (const float*)d_in[2];
    float* out = (float*)d_out;

    const int N = in_sizes[0] / NP;  // 500000

    cudaFuncSetAttribute(build_R_kernel,
                         cudaFuncAttributeMaxDynamicSharedMemorySize, BR_SMEM);
    build_R_kernel<<<1, 256, BR_SMEM>>>(angles, mus);

    cudaFuncSetAttribute(apply_mma_kernel,
                         cudaFuncAttributeMaxDynamicSharedMemorySize, APPLY_SMEM);
    const int grid = (N + CPB - 1) / CPB;  // 1954
    apply_mma_kernel<<<grid, 256, APPLY_SMEM>>>(X, out, N);
}

// round 15
// speedup vs baseline: 1.0612x; 1.0612x over previous
#include <cuda_runtime.h>
#include <cuda_bf16.h>
#include <cstdint>

#define NP    64
#define NANG  2016     // 64*63/2
#define SEG   504      // NANG / 4
#define PITCH 36       // u32 per staged 64-bf16 column: conflict-free + 16B-aligned
#define CPB   128      // columns per CTA

// Pre-packed m16n8k16 A-fragments of (mus-scaled) R, hi/lo bf16 split.
// Slot = (i_tile*4 + s_ktile)*32 + lane ; .x=a0 .y=a1 .z=a2 .w=a3
__device__ uint4 g_fragH[512];
__device__ uint4 g_fragL[512];

// ---------------------------------------------------------------------------
// helpers
// ---------------------------------------------------------------------------
__device__ __forceinline__ uint32_t pack_bf16x2(float lo, float hi) {
    uint32_t r;
    asm("cvt.rn.bf16x2.f32 %0, %1, %2;" : "=r"(r) : "f"(hi), "f"(lo));
    return r;
}
__device__ __forceinline__ float bf16_hi_val(float v) {
    return __bfloat162float(__float2bfloat16(v));
}
__device__ __forceinline__ void mma_bf16(float& d0, float& d1, float& d2, float& d3,
                                         uint32_t a0, uint32_t a1, uint32_t a2, uint32_t a3,
                                         uint32_t b0, uint32_t b1) {
    asm("mma.sync.aligned.m16n8k16.row.col.f32.bf16.bf16.f32 "
        "{%0,%1,%2,%3}, {%4,%5,%6,%7}, {%8,%9}, {%0,%1,%2,%3};"
        : "+f"(d0), "+f"(d1), "+f"(d2), "+f"(d3)
        : "r"(a0), "r"(a1), "r"(a2), "r"(a3), "r"(b0), "r"(b1));
}

// ---------------------------------------------------------------------------
// Kernel 1: build R = P3*P2*P1*P0 (4 parallel 504-rotation segments, 3 fp32
// matmuls to combine), then emit mus-scaled hi/lo bf16 A-fragments.
// (unchanged from R11 — verified rel_err 4.4e-6)
// ---------------------------------------------------------------------------
#define BR_SMEM (16384 * 5)

__global__ void build_R_kernel(const float* __restrict__ angles,
                               const float* __restrict__ mus) {
    extern __shared__ __align__(16) char smem[];
    float2* cs = reinterpret_cast<float2*>(smem);
    float*  Pm[4];
#pragma unroll
    for (int s = 0; s < 4; ++s) Pm[s] = reinterpret_cast<float*>(smem + 16384 + s * 16384);

    const int tid  = threadIdx.x;
    const int g4   = tid >> 6;
    const int lane = tid & 63;

    for (int a = tid; a < NANG; a += 256) {
        float s, c;
        sincosf(angles[a], &s, &c);
        cs[a] = make_float2(c, s);
    }
    {
        float* Y = Pm[g4];
#pragma unroll
        for (int i = 0; i < NP; ++i) Y[i * NP + lane] = (i == lane) ? 1.0f : 0.0f;
    }
    __syncthreads();

    {
        float* Y = Pm[g4];
        const int segStart = g4 * SEG, segEnd = segStart + SEG;
        int F = 0;
        for (int t = 0; t < NP - 1; ++t) {
            const int fanLen = NP - 1 - t;
            int lo = F > segStart ? F : segStart;
            int hi = (F + fanLen) < segEnd ? (F + fanLen) : segEnd;
            if (lo < hi) {
                float vt = Y[t * NP + lane];
                int idx = lo;
                int ib = t + 1 + (lo - F);
                int cnt = hi - lo;
                const int rem = cnt & 7;
                for (int u = 0; u < rem; ++u) {
                    float2 a = cs[idx + u];
                    float vb = Y[(ib + u) * NP + lane];
                    float nb = fmaf(a.y, vt, a.x * vb);
                    vt = fmaf(a.x, vt, -a.y * vb);
                    Y[(ib + u) * NP + lane] = nb;
                }
                idx += rem; ib += rem;
                for (; idx < hi; ib += 8, idx += 8) {
                    float2 a0 = cs[idx+0], a1 = cs[idx+1], a2 = cs[idx+2], a3 = cs[idx+3];
                    float2 a4 = cs[idx+4], a5 = cs[idx+5], a6 = cs[idx+6], a7 = cs[idx+7];
                    float vb0 = Y[(ib+0)*NP+lane], vb1 = Y[(ib+1)*NP+lane];
                    float vb2 = Y[(ib+2)*NP+lane], vb3 = Y[(ib+3)*NP+lane];
                    float vb4 = Y[(ib+4)*NP+lane], vb5 = Y[(ib+5)*NP+lane];
                    float vb6 = Y[(ib+6)*NP+lane], vb7 = Y[(ib+7)*NP+lane];
                    float nb0 = fmaf(a0.y, vt, a0.x*vb0); vt = fmaf(a0.x, vt, -a0.y*vb0);
                    float nb1 = fmaf(a1.y, vt, a1.x*vb1); vt = fmaf(a1.x, vt, -a1.y*vb1);
                    float nb2 = fmaf(a2.y, vt, a2.x*vb2); vt = fmaf(a2.x, vt, -a2.y*vb2);
                    float nb3 = fmaf(a3.y, vt, a3.x*vb3); vt = fmaf(a3.x, vt, -a3.y*vb3);
                    float nb4 = fmaf(a4.y, vt, a4.x*vb4); vt = fmaf(a4.x, vt, -a4.y*vb4);
                    float nb5 = fmaf(a5.y, vt, a5.x*vb5); vt = fmaf(a5.x, vt, -a5.y*vb5);
                    float nb6 = fmaf(a6.y, vt, a6.x*vb6); vt = fmaf(a6.x, vt, -a6.y*vb6);
                    float nb7 = fmaf(a7.y, vt, a7.x*vb7); vt = fmaf(a7.x, vt, -a7.y*vb7);
                    Y[(ib+0)*NP+lane] = nb0; Y[(ib+1)*NP+lane] = nb1;
                    Y[(ib+2)*NP+lane] = nb2; Y[(ib+3)*NP+lane] = nb3;
                    Y[(ib+4)*NP+lane] = nb4; Y[(ib+5)*NP+lane] = nb5;
                    Y[(ib+6)*NP+lane] = nb6; Y[(ib+7)*NP+lane] = nb7;
                }
                Y[t * NP + lane] = vt;
            }
            F += fanLen;
            if (F >= segEnd) break;
        }
    }
    __syncthreads();

    float* T0   = reinterpret_cast<float*>(smem);
    float* T1   = Pm[0];
    float* Rfin = T0;
    const int mi = tid >> 2;
    const int jq = (tid & 3) * 16;

#define MATMUL(Cm, Am, Bm)                                                       \
    {                                                                            \
        float accm[16];                                                          \
        _Pragma("unroll")                                                        \
        for (int u = 0; u < 16; ++u) accm[u] = 0.0f;                             \
        for (int k = 0; k < NP; ++k) {                                           \
            float av = (Am)[mi * NP + k];                                        \
            const float4* br = reinterpret_cast<const float4*>(&(Bm)[k * NP + jq]); \
            float4 b0 = br[0], b1 = br[1], b2 = br[2], b3 = br[3];               \
            accm[0]  = fmaf(av, b0.x, accm[0]);  accm[1]  = fmaf(av, b0.y, accm[1]);  \
            accm[2]  = fmaf(av, b0.z, accm[2]);  accm[3]  = fmaf(av, b0.w, accm[3]);  \
            accm[4]  = fmaf(av, b1.x, accm[4]);  accm[5]  = fmaf(av, b1.y, accm[5]);  \
            accm[6]  = fmaf(av, b1.z, accm[6]);  accm[7]  = fmaf(av, b1.w, accm[7]);  \
            accm[8]  = fmaf(av, b2.x, accm[8]);  accm[9]  = fmaf(av, b2.y, accm[9]);  \
            accm[10] = fmaf(av, b2.z, accm[10]); accm[11] = fmaf(av, b2.w, accm[11]); \
            accm[12] = fmaf(av, b3.x, accm[12]); accm[13] = fmaf(av, b3.y, accm[13]); \
            accm[14] = fmaf(av, b3.z, accm[14]); accm[15] = fmaf(av, b3.w, accm[15]); \
        }                                                                        \
        __syncthreads();                                                         \
        _Pragma("unroll")                                                        \
        for (int u = 0; u < 16; ++u) (Cm)[mi * NP + jq + u] = accm[u];           \
        __syncthreads();                                                         \
    }

    MATMUL(T0, Pm[1], Pm[0]);
    MATMUL(T1, Pm[2], T0);
    MATMUL(Rfin, Pm[3], T1);
#undef MATMUL

#pragma unroll
    for (int pass = 0; pass < 2; ++pass) {
        const int slot = tid + pass * 256;
        const int is = slot >> 5, ln = slot & 31;
        const int it = is >> 2, s = is & 3;
        const int g = ln >> 2, t = ln & 3;
        const int r0 = 16 * it + g, r1 = r0 + 8;
        const int c0 = 16 * s + 2 * t, c1 = c0 + 8;
        const float m0 = mus[r0], m1 = mus[r1];
        float v00 = Rfin[r0 * NP + c0] * m0,     v01 = Rfin[r0 * NP + c0 + 1] * m0;
        float v10 = Rfin[r1 * NP + c0] * m1,     v11 = Rfin[r1 * NP + c0 + 1] * m1;
        float v02 = Rfin[r0 * NP + c1] * m0,     v03 = Rfin[r0 * NP + c1 + 1] * m0;
        float v12 = Rfin[r1 * NP + c1] * m1,     v13 = Rfin[r1 * NP + c1 + 1] * m1;
        uint4 hi, lo;
        hi.x = pack_bf16x2(v00, v01); hi.y = pack_bf16x2(v10, v11);
        hi.z = pack_bf16x2(v02, v03); hi.w = pack_bf16x2(v12, v13);
        lo.x = pack_bf16x2(v00 - bf16_hi_val(v00), v01 - bf16_hi_val(v01));
        lo.y = pack_bf16x2(v10 - bf16_hi_val(v10), v11 - bf16_hi_val(v11));
        lo.z = pack_bf16x2(v02 - bf16_hi_val(v02), v03 - bf16_hi_val(v03));
        lo.w = pack_bf16x2(v12 - bf16_hi_val(v12), v13 - bf16_hi_val(v13));
        g_fragH[slot] = hi;
        g_fragL[slot] = lo;
    }
}

// ---------------------------------------------------------------------------
// Kernel 2: out[64, N] = R @ X, warp HMMA, hi/lo split, fused 3 passes.
// v5: R13 CTA shape (64 x 128 cols, 53KB smem, 3 CTAs/SM) with BALANCED
// 32x32 warp tiles (2 i-tiles x 4 n-tiles): operand LDS wavefronts per s
// drop 40 -> 32 while acc regs stay 32 f32. Staging identical to R13.
// smem (u32): FRAGH 0, FRAGL 2048, XHI 4096, XLO 8704, total 13312 (53248B).
// ---------------------------------------------------------------------------
#define SM_FRAGH 0
#define SM_FRAGL 2048
#define SM_XHI   4096
#define SM_XLO   8704
#define APPLY_SMEM (13312 * 4)

__global__ __launch_bounds__(256, 3)
void apply_mma_kernel(const float* __restrict__ X,
                      float* __restrict__ out,
                      int N) {
    extern __shared__ __align__(16) uint32_t sm[];
    uint4*    fragH = reinterpret_cast<uint4*>(sm + SM_FRAGH);
    uint4*    fragL = reinterpret_cast<uint4*>(sm + SM_FRAGL);
    uint32_t* Xhi   = sm + SM_XHI;
    uint32_t* Xlo   = sm + SM_XLO;

    const int tid  = threadIdx.x;
    const int wid  = tid >> 5;
    const int lane = tid & 31;
    const int g    = lane >> 2;
    const int t    = lane & 3;
    const int mg   = wid >> 2;    // row group: i-tiles {2mg, 2mg+1}
    const int cg   = wid & 3;     // col group: columns cg*32 .. cg*32+31
    const int col0 = blockIdx.x * CPB;

    // --- Stage pre-packed R fragments (4x LDG.128 + STS.128) ---
    fragH[tid]       = g_fragH[tid];
    fragH[tid + 256] = g_fragH[tid + 256];
    fragL[tid]       = g_fragL[tid];
    fragL[tid + 256] = g_fragL[tid + 256];

    // --- Stage X tile (hi/lo bf16), chunked 2x16 to limit live registers ---
    {
        const int c  = tid & 127;
        const int kh = (tid >> 7) * 32;
        const int cgl = (col0 + c < N) ? (col0 + c) : (N - 1);
        const float* xp = X + cgl;
#pragma unroll
        for (int h = 0; h < 2; ++h) {
            const int kb = kh + h * 16;
            float v[16];
#pragma unroll
            for (int j = 0; j < 16; ++j) v[j] = xp[(size_t)(kb + j) * N];
            uint32_t hb[8], lb[8];
#pragma unroll
            for (int j = 0; j < 8; ++j) {
                float v0 = v[2 * j], v1 = v[2 * j + 1];
                hb[j] = pack_bf16x2(v0, v1);
                lb[j] = pack_bf16x2(v0 - bf16_hi_val(v0), v1 - bf16_hi_val(v1));
            }
            const int base = c * PITCH + (kb >> 1);
            reinterpret_cast<uint4*>(&Xhi[base])[0]     = make_uint4(hb[0], hb[1], hb[2], hb[3]);
            reinterpret_cast<uint4*>(&Xhi[base + 4])[0] = make_uint4(hb[4], hb[5], hb[6], hb[7]);
            reinterpret_cast<uint4*>(&Xlo[base])[0]     = make_uint4(lb[0], lb[1], lb[2], lb[3]);
            reinterpret_cast<uint4*>(&Xlo[base + 4])[0] = make_uint4(lb[4], lb[5], lb[6], lb[7]);
        }
    }
    __syncthreads();

    // --- Accumulators: [i2][ntile][4], 32 f32 regs ---
    float acc[2][4][4];
#pragma unroll
    for (int i = 0; i < 2; ++i)
#pragma unroll
        for (int n = 0; n < 4; ++n)
#pragma unroll
            for (int r = 0; r < 4; ++r) acc[i][n][r] = 0.0f;

    // --- Fused 3-pass main loop: A-frags once per s (4 LDS.128), B once per
    //     (s,nt) (4 LDS.32), 6 MMAs per (s,nt) ---
#pragma unroll
    for (int s = 0; s < 4; ++s) {
        uint4 fH0 = fragH[((2 * mg + 0) * 4 + s) * 32 + lane];
        uint4 fL0 = fragL[((2 * mg + 0) * 4 + s) * 32 + lane];
        uint4 fH1 = fragH[((2 * mg + 1) * 4 + s) * 32 + lane];
        uint4 fL1 = fragL[((2 * mg + 1) * 4 + s) * 32 + lane];

#pragma unroll
        for (int nt = 0; nt < 4; ++nt) {
            const int crow = cg * 32 + nt * 8 + g;
            const int bi = crow * PITCH + s * 8 + t;
            uint32_t bh0 = Xhi[bi];
            uint32_t bh1 = Xhi[bi + 4];
            uint32_t bl0 = Xlo[bi];
            uint32_t bl1 = Xlo[bi + 4];

            mma_bf16(acc[0][nt][0], acc[0][nt][1], acc[0][nt][2], acc[0][nt][3],
                     fH0.x, fH0.y, fH0.z, fH0.w, bh0, bh1);
            mma_bf16(acc[0][nt][0], acc[0][nt][1], acc[0][nt][2], acc[0][nt][3],
                     fH0.x, fH0.y, fH0.z, fH0.w, bl0, bl1);
            mma_bf16(acc[0][nt][0], acc[0][nt][1], acc[0][nt][2], acc[0][nt][3],
                     fL0.x, fL0.y, fL0.z, fL0.w, bh0, bh1);
            mma_bf16(acc[1][nt][0], acc[1][nt][1], acc[1][nt][2], acc[1][nt][3],
                     fH1.x, fH1.y, fH1.z, fH1.w, bh0, bh1);
            mma_bf16(acc[1][nt][0], acc[1][nt][1], acc[1][nt][2], acc[1][nt][3],
                     fH1.x, fH1.y, fH1.z, fH1.w, bl0, bl1);
            mma_bf16(acc[1][nt][0], acc[1][nt][1], acc[1][nt][2], acc[1][nt][3],
                     fL1.x, fL1.y, fL1.z, fL1.w, bh0, bh1);
        }
    }

    // --- Epilogue: adjacent-column float2 stores ---
#pragma unroll
    for (int i = 0; i < 2; ++i) {
        const int row = (2 * mg + i) * 16 + g;
#pragma unroll
        for (int nt = 0; nt < 4; ++nt) {
            const int colb = col0 + cg * 32 + nt * 8 + 2 * t;
            if (colb < N) {
                *reinterpret_cast<float2*>(out + (size_t)row * N + colb) =
                    make_float2(acc[i][nt][0], acc[i][nt][1]);
                *reinterpret_cast<float2*>(out + (size_t)(row + 8) * N + colb) =
                    make_float2(acc[i][nt][2], acc[i][nt][3]);
            }
        }
    }
}

// ---------------------------------------------------------------------------
// Inputs (metadata order): X [64*500000] f32, angles [2016] f32, mus [64] f32.
// Output: [64*500000] f32.
// ---------------------------------------------------------------------------
extern "C" void kernel_launch(void* const* d_in, const int* in_sizes, int n_in,
                              void* d_out, int out_size) {
    const float* X      = (const float*)d_in[0];
    const float* angles = (const float*)d_in[1];
    const float* mus    = (const float*)d_in[2];
    float* out = (float*)d_out;

    const int N = in_sizes[0] / NP;  // 500000

    cudaFuncSetAttribute(build_R_kernel,
                         cudaFuncAttributeMaxDynamicSharedMemorySize, BR_SMEM);
    build_R_kernel<<<1, 256, BR_SMEM>>>(angles, mus);

    cudaFuncSetAttribute(apply_mma_kernel,
                         cudaFuncAttributeMaxDynamicSharedMemorySize, APPLY_SMEM);
    const int grid = (N + CPB - 1) / CPB;  // 3907
    apply_mma_kernel<<<grid, 256, APPLY_SMEM>>>(X, out, N);
}

// round 16
// speedup vs baseline: 1.1047x; 1.0410x over previous
#include <cuda_runtime.h>
#include <cuda_bf16.h>
#include <cstdint>

#define NP    64
#define NANG  2016     // 64*63/2
#define SEG2  1008     // NANG / 2
#define PITCH 36       // u32 per staged 64-bf16 column: conflict-free + 16B-aligned
#define CPB   128      // columns per CTA

// Pre-packed m16n8k16 A-fragments of (mus-scaled) R, hi/lo bf16 split.
__device__ uint4 g_fragH[512];
__device__ uint4 g_fragL[512];

// Election / completion state (reset by the last CTA each launch).
__device__ unsigned g_ticket = 0;
__device__ unsigned g_flag   = 0;
__device__ unsigned g_done   = 0;

// ---------------------------------------------------------------------------
// helpers
// ---------------------------------------------------------------------------
__device__ __forceinline__ uint32_t pack_bf16x2(float lo, float hi) {
    uint32_t r;
    asm("cvt.rn.bf16x2.f32 %0, %1, %2;" : "=r"(r) : "f"(hi), "f"(lo));
    return r;
}
__device__ __forceinline__ float bf16_hi_val(float v) {
    return __bfloat162float(__float2bfloat16(v));
}
__device__ __forceinline__ void mma_bf16(float& d0, float& d1, float& d2, float& d3,
                                         uint32_t a0, uint32_t a1, uint32_t a2, uint32_t a3,
                                         uint32_t b0, uint32_t b1) {
    asm("mma.sync.aligned.m16n8k16.row.col.f32.bf16.bf16.f32 "
        "{%0,%1,%2,%3}, {%4,%5,%6,%7}, {%8,%9}, {%0,%1,%2,%3};"
        : "+f"(d0), "+f"(d1), "+f"(d2), "+f"(d3)
        : "r"(a0), "r"(a1), "r"(a2), "r"(a3), "r"(b0), "r"(b1));
}
__device__ __forceinline__ unsigned ld_acquire_gpu(unsigned* p) {
    unsigned v;
    asm volatile("ld.acquire.gpu.global.u32 %0, [%1];" : "=r"(v) : "l"(p) : "memory");
    return v;
}

// ---------------------------------------------------------------------------
// Device-side build of R = P1 * P0 (two 1008-rotation segments in parallel,
// one 64x64x64 fp32 matmul combine), then emit mus-scaled hi/lo bf16
// A-fragments to global. Runs entirely inside the winner CTA's 53KB smem:
//   cs   : bytes [0, 16384)        (float2[2016]; dead after rotations)
//   Y0   : bytes [16384, 32768)    (P0, 64x64 f32)
//   Y1   : bytes [32768, 49152)    (P1, 64x64 f32)
//   Rfin : bytes [0, 16384)        (reuses cs region)
// ---------------------------------------------------------------------------
__device__ void build_R_device(uint32_t* sm,
                               const float* __restrict__ angles,
                               const float* __restrict__ mus) {
    float2* cs   = reinterpret_cast<float2*>(sm);
    float*  Y0   = reinterpret_cast<float*>(sm + 4096);
    float*  Y1   = reinterpret_cast<float*>(sm + 8192);
    float*  Rfin = reinterpret_cast<float*>(sm);
    const int tid = threadIdx.x;

    for (int a = tid; a < NANG; a += 256) {
        float s, c;
        sincosf(angles[a], &s, &c);
        cs[a] = make_float2(c, s);
    }
    if (tid < 128) {
        const int lane = tid & 63;
        float* Y = (tid >> 6) ? Y1 : Y0;
#pragma unroll
        for (int i = 0; i < NP; ++i) Y[i * NP + lane] = (i == lane) ? 1.0f : 0.0f;
    }
    __syncthreads();

    // --- Segment rotations (2 x 1008), threads 0..127 ---
    if (tid < 128) {
        const int seg  = tid >> 6;
        const int lane = tid & 63;
        float* Y = seg ? Y1 : Y0;
        const int segStart = seg * SEG2, segEnd = segStart + SEG2;
        int F = 0;
        for (int t = 0; t < NP - 1; ++t) {
            const int fanLen = NP - 1 - t;
            int lo = F > segStart ? F : segStart;
            int hi = (F + fanLen) < segEnd ? (F + fanLen) : segEnd;
            if (lo < hi) {
                float vt = Y[t * NP + lane];
                int idx = lo;
                int ib = t + 1 + (lo - F);
                int cnt = hi - lo;
                const int rem = cnt & 7;
                for (int u = 0; u < rem; ++u) {
                    float2 a = cs[idx + u];
                    float vb = Y[(ib + u) * NP + lane];
                    float nb = fmaf(a.y, vt, a.x * vb);
                    vt = fmaf(a.x, vt, -a.y * vb);
                    Y[(ib + u) * NP + lane] = nb;
                }
                idx += rem; ib += rem;
                for (; idx < hi; ib += 8, idx += 8) {
                    float2 a0 = cs[idx+0], a1 = cs[idx+1], a2 = cs[idx+2], a3 = cs[idx+3];
                    float2 a4 = cs[idx+4], a5 = cs[idx+5], a6 = cs[idx+6], a7 = cs[idx+7];
                    float vb0 = Y[(ib+0)*NP+lane], vb1 = Y[(ib+1)*NP+lane];
                    float vb2 = Y[(ib+2)*NP+lane], vb3 = Y[(ib+3)*NP+lane];
                    float vb4 = Y[(ib+4)*NP+lane], vb5 = Y[(ib+5)*NP+lane];
                    float vb6 = Y[(ib+6)*NP+lane], vb7 = Y[(ib+7)*NP+lane];
                    float nb0 = fmaf(a0.y, vt, a0.x*vb0); vt = fmaf(a0.x, vt, -a0.y*vb0);
                    float nb1 = fmaf(a1.y, vt, a1.x*vb1); vt = fmaf(a1.x, vt, -a1.y*vb1);
                    float nb2 = fmaf(a2.y, vt, a2.x*vb2); vt = fmaf(a2.x, vt, -a2.y*vb2);
                    float nb3 = fmaf(a3.y, vt, a3.x*vb3); vt = fmaf(a3.x, vt, -a3.y*vb3);
                    float nb4 = fmaf(a4.y, vt, a4.x*vb4); vt = fmaf(a4.x, vt, -a4.y*vb4);
                    float nb5 = fmaf(a5.y, vt, a5.x*vb5); vt = fmaf(a5.x, vt, -a5.y*vb5);
                    float nb6 = fmaf(a6.y, vt, a6.x*vb6); vt = fmaf(a6.x, vt, -a6.y*vb6);
                    float nb7 = fmaf(a7.y, vt, a7.x*vb7); vt = fmaf(a7.x, vt, -a7.y*vb7);
                    Y[(ib+0)*NP+lane] = nb0; Y[(ib+1)*NP+lane] = nb1;
                    Y[(ib+2)*NP+lane] = nb2; Y[(ib+3)*NP+lane] = nb3;
                    Y[(ib+4)*NP+lane] = nb4; Y[(ib+5)*NP+lane] = nb5;
                    Y[(ib+6)*NP+lane] = nb6; Y[(ib+7)*NP+lane] = nb7;
                }
                Y[t * NP + lane] = vt;
            }
            F += fanLen;
            if (F >= segEnd) break;
        }
    }
    __syncthreads();

    // --- Combine: Rfin = Y1 * Y0 (all 256 threads, 16 outputs each) ---
    {
        const int mi = tid >> 2;
        const int jq = (tid & 3) * 16;
        float accm[16];
#pragma unroll
        for (int u = 0; u < 16; ++u) accm[u] = 0.0f;
        for (int k = 0; k < NP; ++k) {
            float av = Y1[mi * NP + k];
            const float4* br = reinterpret_cast<const float4*>(&Y0[k * NP + jq]);
            float4 b0 = br[0], b1 = br[1], b2 = br[2], b3 = br[3];
            accm[0]  = fmaf(av, b0.x, accm[0]);  accm[1]  = fmaf(av, b0.y, accm[1]);
            accm[2]  = fmaf(av, b0.z, accm[2]);  accm[3]  = fmaf(av, b0.w, accm[3]);
            accm[4]  = fmaf(av, b1.x, accm[4]);  accm[5]  = fmaf(av, b1.y, accm[5]);
            accm[6]  = fmaf(av, b1.z, accm[6]);  accm[7]  = fmaf(av, b1.w, accm[7]);
            accm[8]  = fmaf(av, b2.x, accm[8]);  accm[9]  = fmaf(av, b2.y, accm[9]);
            accm[10] = fmaf(av, b2.z, accm[10]); accm[11] = fmaf(av, b2.w, accm[11]);
            accm[12] = fmaf(av, b3.x, accm[12]); accm[13] = fmaf(av, b3.y, accm[13]);
            accm[14] = fmaf(av, b3.z, accm[14]); accm[15] = fmaf(av, b3.w, accm[15]);
        }
        __syncthreads();   // cs region dead; safe to overwrite with Rfin
#pragma unroll
        for (int u = 0; u < 16; ++u) Rfin[mi * NP + jq + u] = accm[u];
        __syncthreads();
    }

    // --- Emit mus-scaled hi/lo fragments: 512 slots, 2 per thread ---
#pragma unroll
    for (int pass = 0; pass < 2; ++pass) {
        const int slot = tid + pass * 256;
        const int is = slot >> 5, ln = slot & 31;
        const int it = is >> 2, s = is & 3;
        const int g = ln >> 2, t = ln & 3;
        const int r0 = 16 * it + g, r1 = r0 + 8;
        const int c0 = 16 * s + 2 * t, c1 = c0 + 8;
        const float m0 = mus[r0], m1 = mus[r1];
        float v00 = Rfin[r0 * NP + c0] * m0,     v01 = Rfin[r0 * NP + c0 + 1] * m0;
        float v10 = Rfin[r1 * NP + c0] * m1,     v11 = Rfin[r1 * NP + c0 + 1] * m1;
        float v02 = Rfin[r0 * NP + c1] * m0,     v03 = Rfin[r0 * NP + c1 + 1] * m0;
        float v12 = Rfin[r1 * NP + c1] * m1,     v13 = Rfin[r1 * NP + c1 + 1] * m1;
        uint4 hi, lo;
        hi.x = pack_bf16x2(v00, v01); hi.y = pack_bf16x2(v10, v11);
        hi.z = pack_bf16x2(v02, v03); hi.w = pack_bf16x2(v12, v13);
        lo.x = pack_bf16x2(v00 - bf16_hi_val(v00), v01 - bf16_hi_val(v01));
        lo.y = pack_bf16x2(v10 - bf16_hi_val(v10), v11 - bf16_hi_val(v11));
        lo.z = pack_bf16x2(v02 - bf16_hi_val(v02), v03 - bf16_hi_val(v03));
        lo.w = pack_bf16x2(v12 - bf16_hi_val(v12), v13 - bf16_hi_val(v13));
        g_fragH[slot] = hi;
        g_fragL[slot] = lo;
    }
}

// ---------------------------------------------------------------------------
// Fused kernel: first CTA to run (atomicCAS election) builds R + fragments,
// sets a flag; all other CTAs stage their X tile FIRST (independent of R,
// overlapping the build), then spin-wait, then run the R15 HMMA main loop.
// Last CTA resets election state so every graph replay rebuilds.
// smem (u32): FRAGH 0, FRAGL 2048, XHI 4096, XLO 8704, total 13312 (53248B).
// ---------------------------------------------------------------------------
#define SM_FRAGH 0
#define SM_FRAGL 2048
#define SM_XHI   4096
#define SM_XLO   8704
#define APPLY_SMEM (13312 * 4)

__global__ __launch_bounds__(256, 3)
void fused_kernel(const float* __restrict__ X,
                  const float* __restrict__ angles,
                  const float* __restrict__ mus,
                  float* __restrict__ out,
                  int N) {
    extern __shared__ __align__(16) uint32_t sm[];
    uint4*    fragH = reinterpret_cast<uint4*>(sm + SM_FRAGH);
    uint4*    fragL = reinterpret_cast<uint4*>(sm + SM_FRAGL);
    uint32_t* Xhi   = sm + SM_XHI;
    uint32_t* Xlo   = sm + SM_XLO;

    const int tid  = threadIdx.x;
    const int wid  = tid >> 5;
    const int lane = tid & 31;
    const int g    = lane >> 2;
    const int t    = lane & 3;
    const int mg   = wid >> 2;
    const int cg   = wid & 3;
    const int col0 = blockIdx.x * CPB;

    __shared__ unsigned s_winner;
    if (tid == 0) s_winner = (atomicCAS(&g_ticket, 0u, 1u) == 0u) ? 1u : 0u;
    __syncthreads();

    if (s_winner) {
        build_R_device(sm, angles, mus);   // uses all 53KB smem as scratch
        __threadfence();
        __syncthreads();
        if (tid == 0) atomicExch(&g_flag, 1u);
    }

    // --- Stage X tile (hi/lo bf16) — independent of R, overlaps the build ---
    {
        const int c  = tid & 127;
        const int kh = (tid >> 7) * 32;
        const int cgl = (col0 + c < N) ? (col0 + c) : (N - 1);
        const float* xp = X + cgl;
#pragma unroll
        for (int h = 0; h < 2; ++h) {
            const int kb = kh + h * 16;
            float v[16];
#pragma unroll
            for (int j = 0; j < 16; ++j) v[j] = xp[(size_t)(kb + j) * N];
            uint32_t hb[8], lb[8];
#pragma unroll
            for (int j = 0; j < 8; ++j) {
                float v0 = v[2 * j], v1 = v[2 * j + 1];
                hb[j] = pack_bf16x2(v0, v1);
                lb[j] = pack_bf16x2(v0 - bf16_hi_val(v0), v1 - bf16_hi_val(v1));
            }
            const int base = c * PITCH + (kb >> 1);
            reinterpret_cast<uint4*>(&Xhi[base])[0]     = make_uint4(hb[0], hb[1], hb[2], hb[3]);
            reinterpret_cast<uint4*>(&Xhi[base + 4])[0] = make_uint4(hb[4], hb[5], hb[6], hb[7]);
            reinterpret_cast<uint4*>(&Xlo[base])[0]     = make_uint4(lb[0], lb[1], lb[2], lb[3]);
            reinterpret_cast<uint4*>(&Xlo[base + 4])[0] = make_uint4(lb[4], lb[5], lb[6], lb[7]);
        }
    }

    // --- Wait for the build (non-winners) ---
    if (!s_winner) {
        if (tid == 0) {
            while (ld_acquire_gpu(&g_flag) == 0u) __nanosleep(200);
            __threadfence();
        }
    }
    __syncthreads();

    // --- Stage fragments (L1-bypass loads: data written by another CTA) ---
    fragH[tid]       = __ldcg(&g_fragH[tid]);
    fragH[tid + 256] = __ldcg(&g_fragH[tid + 256]);
    fragL[tid]       = __ldcg(&g_fragL[tid]);
    fragL[tid + 256] = __ldcg(&g_fragL[tid + 256]);
    __syncthreads();

    // --- Accumulators: [i2][ntile][4] ---
    float acc[2][4][4];
#pragma unroll
    for (int i = 0; i < 2; ++i)
#pragma unroll
        for (int n = 0; n < 4; ++n)
#pragma unroll
            for (int r = 0; r < 4; ++r) acc[i][n][r] = 0.0f;

    // --- Fused 3-pass main loop (R15): 32x32 warp tiles ---
#pragma unroll
    for (int s = 0; s < 4; ++s) {
        uint4 fH0 = fragH[((2 * mg + 0) * 4 + s) * 32 + lane];
        uint4 fL0 = fragL[((2 * mg + 0) * 4 + s) * 32 + lane];
        uint4 fH1 = fragH[((2 * mg + 1) * 4 + s) * 32 + lane];
        uint4 fL1 = fragL[((2 * mg + 1) * 4 + s) * 32 + lane];

#pragma unroll
        for (int nt = 0; nt < 4; ++nt) {
            const int crow = cg * 32 + nt * 8 + g;
            const int bi = crow * PITCH + s * 8 + t;
            uint32_t bh0 = Xhi[bi];
            uint32_t bh1 = Xhi[bi + 4];
            uint32_t bl0 = Xlo[bi];
            uint32_t bl1 = Xlo[bi + 4];

            mma_bf16(acc[0][nt][0], acc[0][nt][1], acc[0][nt][2], acc[0][nt][3],
                     fH0.x, fH0.y, fH0.z, fH0.w, bh0, bh1);
            mma_bf16(acc[0][nt][0], acc[0][nt][1], acc[0][nt][2], acc[0][nt][3],
                     fH0.x, fH0.y, fH0.z, fH0.w, bl0, bl1);
            mma_bf16(acc[0][nt][0], acc[0][nt][1], acc[0][nt][2], acc[0][nt][3],
                     fL0.x, fL0.y, fL0.z, fL0.w, bh0, bh1);
            mma_bf16(acc[1][nt][0], acc[1][nt][1], acc[1][nt][2], acc[1][nt][3],
                     fH1.x, fH1.y, fH1.z, fH1.w, bh0, bh1);
            mma_bf16(acc[1][nt][0], acc[1][nt][1], acc[1][nt][2], acc[1][nt][3],
                     fH1.x, fH1.y, fH1.z, fH1.w, bl0, bl1);
            mma_bf16(acc[1][nt][0], acc[1][nt][1], acc[1][nt][2], acc[1][nt][3],
                     fL1.x, fL1.y, fL1.z, fL1.w, bh0, bh1);
        }
    }

    // --- Epilogue: adjacent-column float2 stores ---
#pragma unroll
    for (int i = 0; i < 2; ++i) {
        const int row = (2 * mg + i) * 16 + g;
#pragma unroll
        for (int nt = 0; nt < 4; ++nt) {
            const int colb = col0 + cg * 32 + nt * 8 + 2 * t;
            if (colb < N) {
                *reinterpret_cast<float2*>(out + (size_t)row * N + colb) =
                    make_float2(acc[i][nt][0], acc[i][nt][1]);
                *reinterpret_cast<float2*>(out + (size_t)(row + 8) * N + colb) =
                    make_float2(acc[i][nt][2], acc[i][nt][3]);
            }
        }
    }

    // --- Completion: last CTA resets election state for the next replay ---
    if (tid == 0) {
        unsigned d = atomicAdd(&g_done, 1u);
        if (d == gridDim.x - 1u) {
            atomicExch(&g_flag, 0u);
            atomicExch(&g_ticket, 0u);
            atomicExch(&g_done, 0u);
        }
    }
}

// ---------------------------------------------------------------------------
// Inputs (metadata order): X [64*500000] f32, angles [2016] f32, mus [64] f32.
// Output: [64*500000] f32.
// ---------------------------------------------------------------------------
extern "C" void kernel_launch(void* const* d_in, const int* in_sizes, int n_in,
                              void* d_out, int out_size) {
    const float* X      = (const float*)d_in[0];
    const float* angles = (const float*)d_in[1];
    const float* mus    = (const float*)d_in[2];
    float* out = (float*)d_out;

    const int N = in_sizes[0] / NP;  // 500000

    cudaFuncSetAttribute(fused_kernel,
                         cudaFuncAttributeMaxDynamicSharedMemorySize, APPLY_SMEM);
    const int grid = (N + CPB - 1) / CPB;  // 3907
    fused_kernel<<<grid, 256, APPLY_SMEM>>>(X, angles, mus, out, N);
}